// round 3
// baseline (speedup 1.0000x reference)
#include <cuda_runtime.h>

// ---------------- problem constants ----------------
#define NN_MAX 50000
#define E_MAX  400000
#define ET_MAX (E_MAX + NN_MAX)
#define FIN    128
#define D1     512
#define HIDC   64
#define HEADS  8
#define NEG    0.2f

// ---------------- scratch (static device globals; no runtime alloc) ----------------
__device__ float    g_H1 [NN_MAX * (size_t)D1];
__device__ float    g_H1A[NN_MAX * (size_t)D1];
__device__ float    g_H2 [NN_MAX * (size_t)HIDC];
__device__ float    g_ALS1[NN_MAX * HEADS];
__device__ float    g_ALD1[NN_MAX * HEADS];
__device__ unsigned g_EMAX1[NN_MAX * HEADS];
__device__ float    g_DEN1[NN_MAX * HEADS];
__device__ float    g_ALS2[NN_MAX];
__device__ float    g_ALD2[NN_MAX];
__device__ unsigned g_EMAX2[NN_MAX];
__device__ float    g_DEN2[NN_MAX];
__device__ int      g_SRC[E_MAX];
__device__ int      g_DST[E_MAX];
__device__ int      g_DEG[NN_MAX];
__device__ int      g_ROFF[NN_MAX + 1];
__device__ int      g_CUR[NN_MAX];
__device__ int      g_CSRS[ET_MAX];
__device__ int      g_FLAG64;

// ---------------- helpers ----------------
__device__ __forceinline__ float lrelu(float x) { return x > 0.f ? x : NEG * x; }

// order-preserving float<->unsigned encoding for atomicMax on floats
__device__ __forceinline__ unsigned fenc(float f) {
    unsigned u = __float_as_uint(f);
    return (u & 0x80000000u) ? ~u : (u | 0x80000000u);
}
__device__ __forceinline__ float fdec(unsigned u) {
    return (u & 0x80000000u) ? __uint_as_float(u ^ 0x80000000u)
                             : __uint_as_float(~u);
}

// ---------------- edge dtype detection + conversion ----------------
__global__ void k_detect(const int* __restrict__ p, int E) {
    __shared__ int nz;
    if (threadIdx.x == 0) nz = 0;
    __syncthreads();
    int total = 2 * E; if (total > 4096) total = 4096;
    int local = 0;
    for (int i = 2 * (int)threadIdx.x + 1; i < total; i += 2 * (int)blockDim.x)
        local |= p[i];
    if (local) atomicOr(&nz, 1);
    __syncthreads();
    if (threadIdx.x == 0) g_FLAG64 = (nz == 0) ? 1 : 0;  // all-hi-words-zero => int64
}

__global__ void k_convert(const void* __restrict__ buf, int E) {
    int i = blockIdx.x * blockDim.x + threadIdx.x;
    if (i >= E) return;
    if (g_FLAG64) {
        const long long* p = (const long long*)buf;
        g_SRC[i] = (int)p[i];
        g_DST[i] = (int)p[E + i];
    } else {
        const int* p = (const int*)buf;
        g_SRC[i] = p[i];
        g_DST[i] = p[E + i];
    }
}

// ---------------- fills ----------------
__global__ void k_fill_i(int* p, int v, int n) {
    int i = blockIdx.x * blockDim.x + threadIdx.x;
    if (i < n) p[i] = v;
}
__global__ void k_fill_attn1(int n) {  // EMAX1=0u (== -inf encoded), DEN1=0
    int i = blockIdx.x * blockDim.x + threadIdx.x;
    if (i < n) { g_EMAX1[i] = 0u; g_DEN1[i] = 0.f; }
}
__global__ void k_fill_attn2(int n) {
    int i = blockIdx.x * blockDim.x + threadIdx.x;
    if (i < n) { g_EMAX2[i] = 0u; g_DEN2[i] = 0.f; }
}

// ---------------- CSR build ----------------
__global__ void k_degree(int E, int Et) {
    int i = blockIdx.x * blockDim.x + threadIdx.x;
    if (i >= Et) return;
    int d = (i < E) ? g_DST[i] : (i - E);
    atomicAdd(&g_DEG[d], 1);
}

__global__ void k_scan(int NN) {  // 1 block, 1024 threads
    __shared__ int sums[1024];
    int t = threadIdx.x;
    int chunk = (NN + 1023) >> 10;
    int beg = t * chunk;
    int end = beg + chunk; if (end > NN) end = NN;
    int s = 0;
    for (int i = beg; i < end; i++) s += g_DEG[i];
    sums[t] = s;
    __syncthreads();
    for (int off = 1; off < 1024; off <<= 1) {
        int v = (t >= off) ? sums[t - off] : 0;
        __syncthreads();
        sums[t] += v;
        __syncthreads();
    }
    int run = (t == 0) ? 0 : sums[t - 1];
    for (int i = beg; i < end; i++) {
        int d = g_DEG[i];
        g_ROFF[i] = run;
        g_CUR[i]  = run;
        run += d;
    }
    if (t == 0) g_ROFF[NN] = sums[1023];
}

__global__ void k_scatter(int E, int Et) {
    int i = blockIdx.x * blockDim.x + threadIdx.x;
    if (i >= Et) return;
    int s, d;
    if (i < E) { s = g_SRC[i]; d = g_DST[i]; }
    else       { s = d = i - E; }
    int pos = atomicAdd(&g_CUR[d], 1);
    g_CSRS[pos] = s;
}

// ---------------- SGEMM: C[M,N] = A[M,K] @ B[K,N], row-major, fp32 ----------------
// BM=BN=64, BK=16, 256 threads, 4x4 per thread. K % 16 == 0, N % 64 == 0 required.
__global__ __launch_bounds__(256) void sgemm64(
    const float* __restrict__ A, const float* __restrict__ B, float* __restrict__ C,
    int M, int N, int K)
{
    __shared__ float As[16][64];
    __shared__ float Bs[16][64];
    int t  = threadIdx.x;
    int m0 = blockIdx.y * 64;
    int n0 = blockIdx.x * 64;
    int tx = t & 15, ty = t >> 4;

    float acc[4][4] = {};

    int arow  = t >> 2;         // 0..63
    int acol4 = (t & 3) * 4;    // 0,4,8,12
    int am = m0 + arow; if (am >= M) am = M - 1;
    int brow  = t >> 4;         // 0..15
    int bcol4 = (t & 15) * 4;   // 0..60

    for (int k0 = 0; k0 < K; k0 += 16) {
        float4 av = *(const float4*)(A + (size_t)am * K + k0 + acol4);
        As[acol4 + 0][arow] = av.x;
        As[acol4 + 1][arow] = av.y;
        As[acol4 + 2][arow] = av.z;
        As[acol4 + 3][arow] = av.w;
        float4 bv = *(const float4*)(B + (size_t)(k0 + brow) * N + n0 + bcol4);
        *(float4*)&Bs[brow][bcol4] = bv;
        __syncthreads();
#pragma unroll
        for (int k = 0; k < 16; k++) {
            float4 a = *(const float4*)&As[k][ty * 4];
            float4 b = *(const float4*)&Bs[k][tx * 4];
            acc[0][0] += a.x * b.x; acc[0][1] += a.x * b.y; acc[0][2] += a.x * b.z; acc[0][3] += a.x * b.w;
            acc[1][0] += a.y * b.x; acc[1][1] += a.y * b.y; acc[1][2] += a.y * b.z; acc[1][3] += a.y * b.w;
            acc[2][0] += a.z * b.x; acc[2][1] += a.z * b.y; acc[2][2] += a.z * b.z; acc[2][3] += a.z * b.w;
            acc[3][0] += a.w * b.x; acc[3][1] += a.w * b.y; acc[3][2] += a.w * b.z; acc[3][3] += a.w * b.w;
        }
        __syncthreads();
    }
#pragma unroll
    for (int i = 0; i < 4; i++) {
        int m = m0 + ty * 4 + i;
        if (m < M) {
            float* cp = C + (size_t)m * N + n0 + tx * 4;
            cp[0] = acc[i][0]; cp[1] = acc[i][1]; cp[2] = acc[i][2]; cp[3] = acc[i][3];
        }
    }
}

// ---------------- layer 1 attention logits per node ----------------
__global__ __launch_bounds__(256) void k_al1(
    const float* __restrict__ asrc, const float* __restrict__ adst, int NN)
{
    int n = blockIdx.x;
    int t = threadIdx.x;
    int h = t >> 5, lane = t & 31;
    const float* hp = g_H1 + (size_t)n * D1 + h * 64;
    float v0 = hp[lane], v1 = hp[lane + 32];
    float s = v0 * asrc[h * 64 + lane] + v1 * asrc[h * 64 + lane + 32];
    float d = v0 * adst[h * 64 + lane] + v1 * adst[h * 64 + lane + 32];
#pragma unroll
    for (int o = 16; o; o >>= 1) {
        s += __shfl_down_sync(0xffffffffu, s, o);
        d += __shfl_down_sync(0xffffffffu, d, o);
    }
    if (lane == 0) { g_ALS1[n * HEADS + h] = s; g_ALD1[n * HEADS + h] = d; }
}

// ---------------- layer 1 edge softmax stats ----------------
__global__ void k_emax1(int E, int Et) {
    int i = blockIdx.x * blockDim.x + threadIdx.x;
    if (i >= Et * HEADS) return;
    int e = i >> 3, h = i & 7;
    int s, d;
    if (e < E) { s = g_SRC[e]; d = g_DST[e]; } else { s = d = e - E; }
    float v = lrelu(g_ALS1[s * HEADS + h] + g_ALD1[d * HEADS + h]);
    atomicMax(&g_EMAX1[d * HEADS + h], fenc(v));
}
__global__ void k_eden1(int E, int Et) {
    int i = blockIdx.x * blockDim.x + threadIdx.x;
    if (i >= Et * HEADS) return;
    int e = i >> 3, h = i & 7;
    int s, d;
    if (e < E) { s = g_SRC[e]; d = g_DST[e]; } else { s = d = e - E; }
    float v = lrelu(g_ALS1[s * HEADS + h] + g_ALD1[d * HEADS + h]);
    float ex = __expf(v - fdec(g_EMAX1[d * HEADS + h]));
    atomicAdd(&g_DEN1[d * HEADS + h], ex);
}

// ---------------- layer 1 aggregation (+ bias + relu) ----------------
__global__ __launch_bounds__(512) void k_agg1(const float* __restrict__ b1, int NN) {
    int n = blockIdx.x;
    int t = threadIdx.x;           // 0..511, h = t/64
    int h = t >> 6;
    float ald = g_ALD1[n * HEADS + h];
    float em  = fdec(g_EMAX1[n * HEADS + h]);
    float inv = 1.f / g_DEN1[n * HEADS + h];
    int j0 = g_ROFF[n], j1 = g_ROFF[n + 1];
    float acc = 0.f;
    for (int j = j0; j < j1; j++) {
        int s = g_CSRS[j];
        float e = lrelu(g_ALS1[s * HEADS + h] + ald);
        float alpha = __expf(e - em) * inv;
        acc += alpha * g_H1[(size_t)s * D1 + t];
    }
    acc += b1[t];
    g_H1A[(size_t)n * D1 + t] = acc > 0.f ? acc : 0.f;
}

// ---------------- layer 2 attention logits ----------------
__global__ __launch_bounds__(32) void k_al2(
    const float* __restrict__ asrc, const float* __restrict__ adst, int NN)
{
    int n = blockIdx.x;
    int lane = threadIdx.x;
    const float* hp = g_H2 + (size_t)n * HIDC;
    float v0 = hp[lane], v1 = hp[lane + 32];
    float s = v0 * asrc[lane] + v1 * asrc[lane + 32];
    float d = v0 * adst[lane] + v1 * adst[lane + 32];
#pragma unroll
    for (int o = 16; o; o >>= 1) {
        s += __shfl_down_sync(0xffffffffu, s, o);
        d += __shfl_down_sync(0xffffffffu, d, o);
    }
    if (lane == 0) { g_ALS2[n] = s; g_ALD2[n] = d; }
}

__global__ void k_emax2(int E, int Et) {
    int i = blockIdx.x * blockDim.x + threadIdx.x;
    if (i >= Et) return;
    int s, d;
    if (i < E) { s = g_SRC[i]; d = g_DST[i]; } else { s = d = i - E; }
    float v = lrelu(g_ALS2[s] + g_ALD2[d]);
    atomicMax(&g_EMAX2[d], fenc(v));
}
__global__ void k_eden2(int E, int Et) {
    int i = blockIdx.x * blockDim.x + threadIdx.x;
    if (i >= Et) return;
    int s, d;
    if (i < E) { s = g_SRC[i]; d = g_DST[i]; } else { s = d = i - E; }
    float v = lrelu(g_ALS2[s] + g_ALD2[d]);
    atomicAdd(&g_DEN2[d], __expf(v - fdec(g_EMAX2[d])));
}

// ---------------- layer 2 aggregation + relu + final projection ----------------
__global__ __launch_bounds__(64) void k_agg2(
    const float* __restrict__ b2, const float* __restrict__ Wc,
    const float* __restrict__ bc, float* __restrict__ out, int NN)
{
    int n = blockIdx.x;
    int t = threadIdx.x;  // channel
    float ald = g_ALD2[n];
    float em  = fdec(g_EMAX2[n]);
    float inv = 1.f / g_DEN2[n];
    int j0 = g_ROFF[n], j1 = g_ROFF[n + 1];
    float acc = 0.f;
    for (int j = j0; j < j1; j++) {
        int s = g_CSRS[j];
        float e = lrelu(g_ALS2[s] + ald);
        float alpha = __expf(e - em) * inv;
        acc += alpha * g_H2[(size_t)s * HIDC + t];
    }
    float v = acc + b2[t];
    v = v > 0.f ? v : 0.f;
    v *= Wc[t];
#pragma unroll
    for (int o = 16; o; o >>= 1) v += __shfl_down_sync(0xffffffffu, v, o);
    __shared__ float sw[2];
    if ((t & 31) == 0) sw[t >> 5] = v;
    __syncthreads();
    if (t == 0) out[n] = sw[0] + sw[1] + bc[0];
}

// ---------------- host launcher ----------------
extern "C" void kernel_launch(void* const* d_in, const int* in_sizes, int n_in,
                              void* d_out, int out_size)
{
    const float* x     = (const float*)d_in[0];
    const void*  eidx  = d_in[1];
    const float* W1    = (const float*)d_in[2];
    const float* asrc1 = (const float*)d_in[3];
    const float* adst1 = (const float*)d_in[4];
    const float* b1    = (const float*)d_in[5];
    const float* W2    = (const float*)d_in[6];
    const float* asrc2 = (const float*)d_in[7];
    const float* adst2 = (const float*)d_in[8];
    const float* b2    = (const float*)d_in[9];
    const float* Wc    = (const float*)d_in[10];
    const float* bc    = (const float*)d_in[11];
    float* out = (float*)d_out;

    int NN = in_sizes[0] / FIN;  if (NN > NN_MAX) NN = NN_MAX;
    int E  = in_sizes[1] / 2;    if (E  > E_MAX)  E  = E_MAX;
    int Et = E + NN;

    const int TB = 256;
    // edge decode
    k_detect<<<1, 256>>>((const int*)eidx, E);
    k_convert<<<(E + TB - 1) / TB, TB>>>(eidx, E);
    // CSR
    k_fill_i<<<(NN + TB - 1) / TB, TB>>>((int*)nullptr == nullptr ? nullptr : nullptr, 0, 0); // no-op guard removed below
    // (replace: zero DEG)
    {
        // zero degree counters
        extern __device__ int g_DEG[];
    }
    k_fill_i<<<(NN + TB - 1) / TB, TB>>>(nullptr, 0, 0);
    // NOTE: the two fill launches above are dead no-ops (n=0); real zeroing follows:
    {
        int* degp = nullptr;
        cudaGetSymbolAddress((void**)&degp, g_DEG);
        k_fill_i<<<(NN + TB - 1) / TB, TB>>>(degp, 0, NN);
    }
    k_degree<<<(Et + TB - 1) / TB, TB>>>(E, Et);
    k_scan<<<1, 1024>>>(NN);
    k_scatter<<<(Et + TB - 1) / TB, TB>>>(E, Et);

    // layer 1
    {
        float *h1p, *h1ap, *h2p;
        cudaGetSymbolAddress((void**)&h1p,  g_H1);
        cudaGetSymbolAddress((void**)&h1ap, g_H1A);
        cudaGetSymbolAddress((void**)&h2p,  g_H2);
        dim3 g1(D1 / 64, (NN + 63) / 64);
        sgemm64<<<g1, 256>>>(x, W1, h1p, NN, D1, FIN);
        k_al1<<<NN, 256>>>(asrc1, adst1, NN);
        k_fill_attn1<<<(NN * HEADS + TB - 1) / TB, TB>>>(NN * HEADS);
        k_emax1<<<(Et * HEADS + TB - 1) / TB, TB>>>(E, Et);
        k_eden1<<<(Et * HEADS + TB - 1) / TB, TB>>>(E, Et);
        k_agg1<<<NN, 512>>>(b1, NN);
        // layer 2
        dim3 g2(HIDC / 64, (NN + 63) / 64);
        sgemm64<<<g2, 256>>>(h1ap, W2, h2p, NN, HIDC, D1);
        k_al2<<<NN, 32>>>(asrc2, adst2, NN);
        k_fill_attn2<<<(NN + TB - 1) / TB, TB>>>(NN);
        k_emax2<<<(Et + TB - 1) / TB, TB>>>(E, Et);
        k_eden2<<<(Et + TB - 1) / TB, TB>>>(E, Et);
        k_agg2<<<NN, 64>>>(b2, Wc, bc, out, NN);
    }
    (void)n_in; (void)out_size;
}

// round 5
// speedup vs baseline: 2.1508x; 2.1508x over previous
#include <cuda_runtime.h>
#include <cstdint>

// ---------------- problem constants ----------------
#define NN_MAX 50000
#define E_MAX  400000
#define ET_MAX (E_MAX + NN_MAX)
#define FIN    128
#define D1     512
#define HIDC   64
#define HEADS  8
#define NEG    0.2f

// ---------------- scratch ----------------
__device__ float    g_H1 [NN_MAX * (size_t)D1];
__device__ float    g_H1A[NN_MAX * (size_t)D1];
__device__ float    g_H2 [NN_MAX * (size_t)HIDC];
__device__ float    g_WT1[D1 * FIN];      // W1^T  [512,128]
__device__ float    g_WT2[HIDC * D1];     // W2^T  [64,512]
__device__ float    g_ALS1[NN_MAX * HEADS];
__device__ float    g_ALD1[NN_MAX * HEADS];
__device__ unsigned g_EMAX1[NN_MAX * HEADS];
__device__ float    g_DEN1[NN_MAX * HEADS];
__device__ float    g_ALS2[NN_MAX];
__device__ float    g_ALD2[NN_MAX];
__device__ unsigned g_EMAX2[NN_MAX];
__device__ float    g_DEN2[NN_MAX];
__device__ int      g_SRC[E_MAX];
__device__ int      g_DST[E_MAX];
__device__ int      g_DEG[NN_MAX];
__device__ int      g_ROFF[NN_MAX + 1];
__device__ int      g_CUR[NN_MAX];
__device__ int      g_CSRS[ET_MAX];
__device__ int      g_FLAG64;

// ---------------- helpers ----------------
__device__ __forceinline__ float lrelu(float x) { return x > 0.f ? x : NEG * x; }
__device__ __forceinline__ unsigned fenc(float f) {
    unsigned u = __float_as_uint(f);
    return (u & 0x80000000u) ? ~u : (u | 0x80000000u);
}
__device__ __forceinline__ float fdec(unsigned u) {
    return (u & 0x80000000u) ? __uint_as_float(u ^ 0x80000000u)
                             : __uint_as_float(~u);
}
__device__ __forceinline__ uint32_t f2tf32(float f) {
    uint32_t r;
    asm("cvt.rna.tf32.f32 %0, %1;" : "=r"(r) : "f"(f));
    return r;
}
__device__ __forceinline__ void mma_tf32(float* c, const uint32_t* a, const uint32_t* b) {
    asm volatile("mma.sync.aligned.m16n8k8.row.col.f32.tf32.tf32.f32 "
        "{%0,%1,%2,%3}, {%4,%5,%6,%7}, {%8,%9}, {%0,%1,%2,%3};"
        : "+f"(c[0]), "+f"(c[1]), "+f"(c[2]), "+f"(c[3])
        : "r"(a[0]), "r"(a[1]), "r"(a[2]), "r"(a[3]), "r"(b[0]), "r"(b[1]));
}

// ---------------- edge dtype detection + conversion ----------------
__global__ void k_detect(const int* __restrict__ p, int E) {
    __shared__ int nz;
    if (threadIdx.x == 0) nz = 0;
    __syncthreads();
    int total = 2 * E; if (total > 4096) total = 4096;
    int local = 0;
    for (int i = 2 * (int)threadIdx.x + 1; i < total; i += 2 * (int)blockDim.x)
        local |= p[i];
    if (local) atomicOr(&nz, 1);
    __syncthreads();
    if (threadIdx.x == 0) g_FLAG64 = (nz == 0) ? 1 : 0;
}
__global__ void k_convert(const void* __restrict__ buf, int E) {
    int i = blockIdx.x * blockDim.x + threadIdx.x;
    if (i >= E) return;
    if (g_FLAG64) {
        const long long* p = (const long long*)buf;
        g_SRC[i] = (int)p[i];
        g_DST[i] = (int)p[E + i];
    } else {
        const int* p = (const int*)buf;
        g_SRC[i] = p[i];
        g_DST[i] = p[E + i];
    }
}

// ---------------- fills / CSR ----------------
__global__ void k_zero_deg(int n) {
    int i = blockIdx.x * blockDim.x + threadIdx.x;
    if (i < n) g_DEG[i] = 0;
}
__global__ void k_fill_attn1(int n) {
    int i = blockIdx.x * blockDim.x + threadIdx.x;
    if (i < n) { g_EMAX1[i] = 0u; g_DEN1[i] = 0.f; }
}
__global__ void k_fill_attn2(int n) {
    int i = blockIdx.x * blockDim.x + threadIdx.x;
    if (i < n) { g_EMAX2[i] = 0u; g_DEN2[i] = 0.f; }
}
__global__ void k_degree(int E, int Et) {
    int i = blockIdx.x * blockDim.x + threadIdx.x;
    if (i >= Et) return;
    int d = (i < E) ? g_DST[i] : (i - E);
    atomicAdd(&g_DEG[d], 1);
}
__global__ void k_scan(int NN) {
    __shared__ int sums[1024];
    int t = threadIdx.x;
    int chunk = (NN + 1023) >> 10;
    int beg = t * chunk;
    int end = beg + chunk; if (end > NN) end = NN;
    int s = 0;
    for (int i = beg; i < end; i++) s += g_DEG[i];
    sums[t] = s;
    __syncthreads();
    for (int off = 1; off < 1024; off <<= 1) {
        int v = (t >= off) ? sums[t - off] : 0;
        __syncthreads();
        sums[t] += v;
        __syncthreads();
    }
    int run = (t == 0) ? 0 : sums[t - 1];
    for (int i = beg; i < end; i++) {
        int d = g_DEG[i];
        g_ROFF[i] = run;
        g_CUR[i]  = run;
        run += d;
    }
    if (t == 0) g_ROFF[NN] = sums[1023];
}
__global__ void k_scatter(int E, int Et) {
    int i = blockIdx.x * blockDim.x + threadIdx.x;
    if (i >= Et) return;
    int s, d;
    if (i < E) { s = g_SRC[i]; d = g_DST[i]; }
    else       { s = d = i - E; }
    int pos = atomicAdd(&g_CUR[d], 1);
    g_CSRS[pos] = s;
}

// ---------------- weight transposes ----------------
__global__ void k_transpose(const float* __restrict__ W, float* __restrict__ WT, int K, int N) {
    __shared__ float tile[32][33];
    int n0 = blockIdx.x * 32, k0 = blockIdx.y * 32;
    int tx = threadIdx.x, ty = threadIdx.y;   // 32 x 8
#pragma unroll
    for (int i = 0; i < 32; i += 8)
        tile[ty + i][tx] = W[(size_t)(k0 + ty + i) * N + n0 + tx];
    __syncthreads();
#pragma unroll
    for (int i = 0; i < 32; i += 8)
        WT[(size_t)(n0 + ty + i) * K + k0 + tx] = tile[tx][ty + i];
}

// ================= GEMM1: H1 = x @ W1  (mma.sync tf32) =================
// Block tile M=128, N=128, K=128 (BK=32). 256 threads, 8 warps (4m x 2n),
// warp tile 32x64. Fused ALS1/ALD1 (CTA's 128 cols == heads 2nb..2nb+1).
// smem (floats): As 128*36 | Bs 128*36 | buf 128*33 | s_as 128 | s_ad 128 | s_als 256 | s_ald 256
#define G1_AS   0
#define G1_BS   4608
#define G1_BUF  9216
#define G1_SAS  13440
#define G1_SAD  13568
#define G1_SALS 13696
#define G1_SALD 13952
#define G1_SMEMF 14208
#define G1_SMEMB (G1_SMEMF * 4)

__global__ __launch_bounds__(256)
void g1_mma(const float* __restrict__ A, const float* __restrict__ asrc,
            const float* __restrict__ adst, int M)
{
    extern __shared__ float sm[];
    uint32_t* As = (uint32_t*)(sm + G1_AS);
    uint32_t* Bs = (uint32_t*)(sm + G1_BS);
    float* buf   = sm + G1_BUF;
    float* s_as  = sm + G1_SAS;
    float* s_ad  = sm + G1_SAD;
    float* s_als = sm + G1_SALS;
    float* s_ald = sm + G1_SALD;

    int tid = threadIdx.x;
    int wid = tid >> 5, lane = tid & 31;
    int wm = wid >> 1, wn = wid & 1;
    int nb = blockIdx.x;              // 0..3
    int m0 = blockIdx.y * 128;

    if (tid < 128) {
        s_as[tid] = asrc[nb * 128 + tid];
        s_ad[tid] = adst[nb * 128 + tid];
    }
    s_als[tid] = 0.f;
    s_ald[tid] = 0.f;

    float acc[2][8][4];
#pragma unroll
    for (int i = 0; i < 2; i++)
#pragma unroll
        for (int j = 0; j < 8; j++)
#pragma unroll
            for (int k = 0; k < 4; k++) acc[i][j][k] = 0.f;

    for (int k0 = 0; k0 < FIN; k0 += 32) {
        // load A tile: 128 rows x 32 cols
#pragma unroll
        for (int it = 0; it < 4; it++) {
            int idx = tid + it * 256;
            int row = idx >> 3, c4 = (idx & 7) * 4;
            int m = m0 + row; if (m >= M) m = M - 1;
            float4 v = *(const float4*)(A + (size_t)m * FIN + k0 + c4);
            uint32_t* p = As + row * 36 + c4;
            p[0] = f2tf32(v.x); p[1] = f2tf32(v.y); p[2] = f2tf32(v.z); p[3] = f2tf32(v.w);
        }
        // load B tile: WT1 rows nb*128 .. +127, cols k0..+31
#pragma unroll
        for (int it = 0; it < 4; it++) {
            int idx = tid + it * 256;
            int row = idx >> 3, c4 = (idx & 7) * 4;
            float4 v = *(const float4*)(g_WT1 + (size_t)(nb * 128 + row) * FIN + k0 + c4);
            uint32_t* p = Bs + row * 36 + c4;
            p[0] = f2tf32(v.x); p[1] = f2tf32(v.y); p[2] = f2tf32(v.z); p[3] = f2tf32(v.w);
        }
        __syncthreads();
#pragma unroll
        for (int kk = 0; kk < 32; kk += 8) {
            uint32_t a[2][4];
#pragma unroll
            for (int mi = 0; mi < 2; mi++) {
                int r = wm * 32 + mi * 16 + (lane >> 2);
                int kb = kk + (lane & 3);
                a[mi][0] = As[r * 36 + kb];
                a[mi][1] = As[(r + 8) * 36 + kb];
                a[mi][2] = As[r * 36 + kb + 4];
                a[mi][3] = As[(r + 8) * 36 + kb + 4];
            }
            uint32_t b[8][2];
#pragma unroll
            for (int ni = 0; ni < 8; ni++) {
                int n = wn * 64 + ni * 8 + (lane >> 2);
                b[ni][0] = Bs[n * 36 + kk + (lane & 3)];
                b[ni][1] = Bs[n * 36 + kk + (lane & 3) + 4];
            }
#pragma unroll
            for (int mi = 0; mi < 2; mi++)
#pragma unroll
                for (int ni = 0; ni < 8; ni++)
                    mma_tf32(acc[mi][ni], a[mi], b[ni]);
        }
        __syncthreads();
    }

    // epilogue: 4 chunks of 32 cols; stage -> coalesced store + fused logits
#pragma unroll
    for (int c = 0; c < 4; c++) {
        if (wn == (c >> 1)) {
#pragma unroll
            for (int mi = 0; mi < 2; mi++)
#pragma unroll
                for (int nl = 0; nl < 4; nl++) {
                    int ni = (c & 1) * 4 + nl;
                    int r0 = wm * 32 + mi * 16 + (lane >> 2);
                    int cc = nl * 8 + (lane & 3) * 2;
                    buf[r0 * 33 + cc]           = acc[mi][ni][0];
                    buf[r0 * 33 + cc + 1]       = acc[mi][ni][1];
                    buf[(r0 + 8) * 33 + cc]     = acc[mi][ni][2];
                    buf[(r0 + 8) * 33 + cc + 1] = acc[mi][ni][3];
                }
        }
        __syncthreads();
        int lh = c >> 1;
#pragma unroll
        for (int it = 0; it < 4; it++) {
            int row = it * 32 + (tid >> 3);
            int c4 = (tid & 7) * 4;
            float vx = buf[row * 33 + c4];
            float vy = buf[row * 33 + c4 + 1];
            float vz = buf[row * 33 + c4 + 2];
            float vw = buf[row * 33 + c4 + 3];
            int cb = c * 32 + c4;
            float p  = vx * s_as[cb] + vy * s_as[cb + 1] + vz * s_as[cb + 2] + vw * s_as[cb + 3];
            float pd = vx * s_ad[cb] + vy * s_ad[cb + 1] + vz * s_ad[cb + 2] + vw * s_ad[cb + 3];
#pragma unroll
            for (int o = 1; o < 8; o <<= 1) {
                p  += __shfl_xor_sync(0xffffffffu, p, o);
                pd += __shfl_xor_sync(0xffffffffu, pd, o);
            }
            if ((tid & 7) == 0) {
                s_als[row * 2 + lh] += p;
                s_ald[row * 2 + lh] += pd;
            }
            int m = m0 + row;
            if (m < M) {
                float4 v = make_float4(vx, vy, vz, vw);
                *(float4*)(g_H1 + (size_t)m * D1 + nb * 128 + cb) = v;
            }
        }
        __syncthreads();
    }
    if (tid < 128) {
        int m = m0 + tid;
        if (m < M) {
            g_ALS1[m * HEADS + nb * 2 + 0] = s_als[tid * 2 + 0];
            g_ALS1[m * HEADS + nb * 2 + 1] = s_als[tid * 2 + 1];
            g_ALD1[m * HEADS + nb * 2 + 0] = s_ald[tid * 2 + 0];
            g_ALD1[m * HEADS + nb * 2 + 1] = s_ald[tid * 2 + 1];
        }
    }
}

// ================= GEMM2: H2 = H1A @ W2  (mma.sync tf32) =================
// Block tile M=128, N=64, K=512 (BK=32). 256 threads, warp grid 4m x 2n,
// warp tile 32x32. Fused ALS2/ALD2 (single head).
__global__ __launch_bounds__(256)
void g2_mma(const float* __restrict__ asrc, const float* __restrict__ adst, int M)
{
    __shared__ uint32_t As[128 * 36];
    __shared__ uint32_t Bs[64 * 36];
    __shared__ float buf[128 * 33];
    __shared__ float s_as[64], s_ad[64];
    __shared__ float s_als[128], s_ald[128];

    int tid = threadIdx.x;
    int wid = tid >> 5, lane = tid & 31;
    int wm = wid >> 1, wn = wid & 1;
    int m0 = blockIdx.x * 128;

    if (tid < 64) { s_as[tid] = asrc[tid]; s_ad[tid] = adst[tid]; }
    if (tid < 128) { s_als[tid] = 0.f; s_ald[tid] = 0.f; }

    float acc[2][4][4];
#pragma unroll
    for (int i = 0; i < 2; i++)
#pragma unroll
        for (int j = 0; j < 4; j++)
#pragma unroll
            for (int k = 0; k < 4; k++) acc[i][j][k] = 0.f;

    for (int k0 = 0; k0 < D1; k0 += 32) {
#pragma unroll
        for (int it = 0; it < 4; it++) {
            int idx = tid + it * 256;
            int row = idx >> 3, c4 = (idx & 7) * 4;
            int m = m0 + row; if (m >= M) m = M - 1;
            float4 v = *(const float4*)(g_H1A + (size_t)m * D1 + k0 + c4);
            uint32_t* p = As + row * 36 + c4;
            p[0] = f2tf32(v.x); p[1] = f2tf32(v.y); p[2] = f2tf32(v.z); p[3] = f2tf32(v.w);
        }
#pragma unroll
        for (int it = 0; it < 2; it++) {
            int idx = tid + it * 256;
            int row = idx >> 3, c4 = (idx & 7) * 4;
            float4 v = *(const float4*)(g_WT2 + (size_t)row * D1 + k0 + c4);
            uint32_t* p = Bs + row * 36 + c4;
            p[0] = f2tf32(v.x); p[1] = f2tf32(v.y); p[2] = f2tf32(v.z); p[3] = f2tf32(v.w);
        }
        __syncthreads();
#pragma unroll
        for (int kk = 0; kk < 32; kk += 8) {
            uint32_t a[2][4];
#pragma unroll
            for (int mi = 0; mi < 2; mi++) {
                int r = wm * 32 + mi * 16 + (lane >> 2);
                int kb = kk + (lane & 3);
                a[mi][0] = As[r * 36 + kb];
                a[mi][1] = As[(r + 8) * 36 + kb];
                a[mi][2] = As[r * 36 + kb + 4];
                a[mi][3] = As[(r + 8) * 36 + kb + 4];
            }
            uint32_t b[4][2];
#pragma unroll
            for (int ni = 0; ni < 4; ni++) {
                int n = wn * 32 + ni * 8 + (lane >> 2);
                b[ni][0] = Bs[n * 36 + kk + (lane & 3)];
                b[ni][1] = Bs[n * 36 + kk + (lane & 3) + 4];
            }
#pragma unroll
            for (int mi = 0; mi < 2; mi++)
#pragma unroll
                for (int ni = 0; ni < 4; ni++)
                    mma_tf32(acc[mi][ni], a[mi], b[ni]);
        }
        __syncthreads();
    }

    // epilogue: 2 chunks of 32 cols
#pragma unroll
    for (int c = 0; c < 2; c++) {
        if (wn == c) {
#pragma unroll
            for (int mi = 0; mi < 2; mi++)
#pragma unroll
                for (int ni = 0; ni < 4; ni++) {
                    int r0 = wm * 32 + mi * 16 + (lane >> 2);
                    int cc = ni * 8 + (lane & 3) * 2;
                    buf[r0 * 33 + cc]           = acc[mi][ni][0];
                    buf[r0 * 33 + cc + 1]       = acc[mi][ni][1];
                    buf[(r0 + 8) * 33 + cc]     = acc[mi][ni][2];
                    buf[(r0 + 8) * 33 + cc + 1] = acc[mi][ni][3];
                }
        }
        __syncthreads();
#pragma unroll
        for (int it = 0; it < 4; it++) {
            int row = it * 32 + (tid >> 3);
            int c4 = (tid & 7) * 4;
            float vx = buf[row * 33 + c4];
            float vy = buf[row * 33 + c4 + 1];
            float vz = buf[row * 33 + c4 + 2];
            float vw = buf[row * 33 + c4 + 3];
            int cb = c * 32 + c4;
            float p  = vx * s_as[cb] + vy * s_as[cb + 1] + vz * s_as[cb + 2] + vw * s_as[cb + 3];
            float pd = vx * s_ad[cb] + vy * s_ad[cb + 1] + vz * s_ad[cb + 2] + vw * s_ad[cb + 3];
#pragma unroll
            for (int o = 1; o < 8; o <<= 1) {
                p  += __shfl_xor_sync(0xffffffffu, p, o);
                pd += __shfl_xor_sync(0xffffffffu, pd, o);
            }
            if ((tid & 7) == 0) { s_als[row] += p; s_ald[row] += pd; }
            int m = m0 + row;
            if (m < M) {
                float4 v = make_float4(vx, vy, vz, vw);
                *(float4*)(g_H2 + (size_t)m * HIDC + cb) = v;
            }
        }
        __syncthreads();
    }
    if (tid < 128) {
        int m = m0 + tid;
        if (m < M) { g_ALS2[m] = s_als[tid]; g_ALD2[m] = s_ald[tid]; }
    }
}

// ---------------- layer 1 edge softmax stats ----------------
__global__ void k_emax1(int E, int Et) {
    int i = blockIdx.x * blockDim.x + threadIdx.x;
    if (i >= Et * HEADS) return;
    int e = i >> 3, h = i & 7;
    int s, d;
    if (e < E) { s = g_SRC[e]; d = g_DST[e]; } else { s = d = e - E; }
    float v = lrelu(g_ALS1[s * HEADS + h] + g_ALD1[d * HEADS + h]);
    atomicMax(&g_EMAX1[d * HEADS + h], fenc(v));
}
__global__ void k_eden1(int E, int Et) {
    int i = blockIdx.x * blockDim.x + threadIdx.x;
    if (i >= Et * HEADS) return;
    int e = i >> 3, h = i & 7;
    int s, d;
    if (e < E) { s = g_SRC[e]; d = g_DST[e]; } else { s = d = e - E; }
    float v = lrelu(g_ALS1[s * HEADS + h] + g_ALD1[d * HEADS + h]);
    atomicAdd(&g_DEN1[d * HEADS + h], __expf(v - fdec(g_EMAX1[d * HEADS + h])));
}

// ---------------- layer 1 aggregation (float4, shared alphas) ----------------
__global__ __launch_bounds__(128) void k_agg1(const float* __restrict__ b1, int NN) {
    __shared__ float s_ald[HEADS], s_em[HEADS], s_inv[HEADS];
    __shared__ float s_alpha[16][8];
    __shared__ int   s_src[16];
    int n = blockIdx.x;
    int t = threadIdx.x;              // channels 4t..4t+3, head = t>>4
    if (t < HEADS) {
        s_ald[t] = g_ALD1[n * HEADS + t];
        s_em[t]  = fdec(g_EMAX1[n * HEADS + t]);
        s_inv[t] = 1.f / g_DEN1[n * HEADS + t];
    }
    __syncthreads();
    int j0 = g_ROFF[n], j1 = g_ROFF[n + 1];
    int h4 = t >> 4;
    float4 acc = make_float4(0.f, 0.f, 0.f, 0.f);
    for (int jb = j0; jb < j1; jb += 16) {
        int cnt = j1 - jb; if (cnt > 16) cnt = 16;
        int jj = t >> 3, hh = t & 7;
        if (jj < cnt) {
            int s = g_CSRS[jb + jj];
            if (hh == 0) s_src[jj] = s;
            float e = lrelu(g_ALS1[s * HEADS + hh] + s_ald[hh]);
            s_alpha[jj][hh] = __expf(e - s_em[hh]) * s_inv[hh];
        }
        __syncthreads();
        for (int q = 0; q < cnt; q++) {
            float a = s_alpha[q][h4];
            float4 hv = *(const float4*)(g_H1 + (size_t)s_src[q] * D1 + 4 * t);
            acc.x += a * hv.x; acc.y += a * hv.y; acc.z += a * hv.z; acc.w += a * hv.w;
        }
        __syncthreads();
    }
    float4 bv = ((const float4*)b1)[t];
    acc.x += bv.x; acc.y += bv.y; acc.z += bv.z; acc.w += bv.w;
    acc.x = acc.x > 0.f ? acc.x : 0.f;
    acc.y = acc.y > 0.f ? acc.y : 0.f;
    acc.z = acc.z > 0.f ? acc.z : 0.f;
    acc.w = acc.w > 0.f ? acc.w : 0.f;
    *(float4*)(g_H1A + (size_t)n * D1 + 4 * t) = acc;
}

// ---------------- layer 2 edge softmax stats ----------------
__global__ void k_emax2(int E, int Et) {
    int i = blockIdx.x * blockDim.x + threadIdx.x;
    if (i >= Et) return;
    int s, d;
    if (i < E) { s = g_SRC[i]; d = g_DST[i]; } else { s = d = i - E; }
    float v = lrelu(g_ALS2[s] + g_ALD2[d]);
    atomicMax(&g_EMAX2[d], fenc(v));
}
__global__ void k_eden2(int E, int Et) {
    int i = blockIdx.x * blockDim.x + threadIdx.x;
    if (i >= Et) return;
    int s, d;
    if (i < E) { s = g_SRC[i]; d = g_DST[i]; } else { s = d = i - E; }
    float v = lrelu(g_ALS2[s] + g_ALD2[d]);
    atomicAdd(&g_DEN2[d], __expf(v - fdec(g_EMAX2[d])));
}

// ---------------- layer 2 aggregation + relu + final projection ----------------
__global__ __launch_bounds__(64) void k_agg2(
    const float* __restrict__ b2, const float* __restrict__ Wc,
    const float* __restrict__ bc, float* __restrict__ out, int NN)
{
    __shared__ float s_alpha[64];
    __shared__ int   s_src[64];
    __shared__ float sw[2];
    int n = blockIdx.x;
    int t = threadIdx.x;
    float ald = g_ALD2[n];
    float em  = fdec(g_EMAX2[n]);
    float inv = 1.f / g_DEN2[n];
    int j0 = g_ROFF[n], j1 = g_ROFF[n + 1];
    float acc = 0.f;
    for (int jb = j0; jb < j1; jb += 64) {
        int cnt = j1 - jb; if (cnt > 64) cnt = 64;
        if (t < cnt) {
            int s = g_CSRS[jb + t];
            s_src[t] = s;
            float e = lrelu(g_ALS2[s] + ald);
            s_alpha[t] = __expf(e - em) * inv;
        }
        __syncthreads();
        for (int q = 0; q < cnt; q++)
            acc += s_alpha[q] * g_H2[(size_t)s_src[q] * HIDC + t];
        __syncthreads();
    }
    float v = acc + b2[t];
    v = v > 0.f ? v : 0.f;
    v *= Wc[t];
#pragma unroll
    for (int o = 16; o; o >>= 1) v += __shfl_down_sync(0xffffffffu, v, o);
    if ((t & 31) == 0) sw[t >> 5] = v;
    __syncthreads();
    if (t == 0) out[n] = sw[0] + sw[1] + bc[0];
}

// ---------------- host launcher ----------------
extern "C" void kernel_launch(void* const* d_in, const int* in_sizes, int n_in,
                              void* d_out, int out_size)
{
    const float* x     = (const float*)d_in[0];
    const void*  eidx  = d_in[1];
    const float* W1    = (const float*)d_in[2];
    const float* asrc1 = (const float*)d_in[3];
    const float* adst1 = (const float*)d_in[4];
    const float* b1    = (const float*)d_in[5];
    const float* W2    = (const float*)d_in[6];
    const float* asrc2 = (const float*)d_in[7];
    const float* adst2 = (const float*)d_in[8];
    const float* b2    = (const float*)d_in[9];
    const float* Wc    = (const float*)d_in[10];
    const float* bc    = (const float*)d_in[11];
    float* out = (float*)d_out;

    int NN = in_sizes[0] / FIN;  if (NN > NN_MAX) NN = NN_MAX;
    int E  = in_sizes[1] / 2;    if (E  > E_MAX)  E  = E_MAX;
    int Et = E + NN;
    int MT = (NN + 127) / 128;
    const int TB = 256;

    cudaFuncSetAttribute(g1_mma, cudaFuncAttributeMaxDynamicSharedMemorySize, G1_SMEMB);

    float *WT1p, *WT2p;
    cudaGetSymbolAddress((void**)&WT1p, g_WT1);
    cudaGetSymbolAddress((void**)&WT2p, g_WT2);

    // edge decode + CSR
    k_detect<<<1, 256>>>((const int*)eidx, E);
    k_convert<<<(E + TB - 1) / TB, TB>>>(eidx, E);
    k_zero_deg<<<(NN + TB - 1) / TB, TB>>>(NN);
    k_degree<<<(Et + TB - 1) / TB, TB>>>(E, Et);
    k_scan<<<1, 1024>>>(NN);
    k_scatter<<<(Et + TB - 1) / TB, TB>>>(E, Et);

    // weight transposes
    {
        dim3 b(32, 8);
        dim3 gt1(D1 / 32, FIN / 32);
        k_transpose<<<gt1, b>>>(W1, WT1p, FIN, D1);
        dim3 gt2(HIDC / 32, D1 / 32);
        k_transpose<<<gt2, b>>>(W2, WT2p, D1, HIDC);
    }

    // layer 1
    {
        dim3 g1(4, MT);
        g1_mma<<<g1, 256, G1_SMEMB>>>(x, asrc1, adst1, NN);
    }
    k_fill_attn1<<<(NN * HEADS + TB - 1) / TB, TB>>>(NN * HEADS);
    k_emax1<<<(Et * HEADS + TB - 1) / TB, TB>>>(E, Et);
    k_eden1<<<(Et * HEADS + TB - 1) / TB, TB>>>(E, Et);
    k_agg1<<<NN, 128>>>(b1, NN);

    // layer 2
    g2_mma<<<MT, 256>>>(asrc2, adst2, NN);
    k_fill_attn2<<<(NN + TB - 1) / TB, TB>>>(NN);
    k_emax2<<<(Et + TB - 1) / TB, TB>>>(E, Et);
    k_eden2<<<(Et + TB - 1) / TB, TB>>>(E, Et);
    k_agg2<<<NN, 64>>>(b2, Wc, bc, out, NN);

    (void)n_in; (void)out_size;
}